// round 2
// baseline (speedup 1.0000x reference)
#include <cuda_runtime.h>
#include <math.h>

// Problem constants
#define BB 4
#define CC 256
#define HH 128
#define WW 128
#define WS 16
#define NWH 8
#define NWW 8
#define NW 64          // windows per image
#define TT 256         // tokens per window
#define NTOK (BB*NW*TT)  // 65536
#define NHEAD 8
#define DH 32
#define DFF 1024

// ---------------- device scratch (allocation-free: __device__ globals) ----------
// NOTE: host code must NEVER pass these names directly as kernel args (that is
// the host shadow -> ATS silently reads host memory on GB300). Addresses are
// resolved with cudaGetSymbolAddress in kernel_launch.
__device__ float g_x  [NTOK*CC];   // current features, token layout (b,w,t,c)
__device__ float g_xp [NTOK*CC];   // x + pos  (also reused as GEMM temp y)
__device__ float g_q  [NTOK*CC];
__device__ float g_k  [NTOK*CC];
__device__ float g_v  [NTOK*CC];
__device__ float g_att[NTOK*CC];
__device__ float g_src[NTOK*CC];
__device__ float g_ff [NTOK*DFF];
__device__ float g_pos[NW*TT*CC];
__device__ float g_rel[TT*CC];
__device__ float g_valid[BB*NW];

// ---------------- rel position MLP:  [T,2] -> relu(64) -> [T,C] -----------------
__global__ void rel_kernel(const float* __restrict__ w1, const float* __restrict__ b1,
                           const float* __restrict__ w2, const float* __restrict__ b2)
{
    __shared__ float hid[64];
    int t = blockIdx.x;
    float cy = (float)(t / WS) / (float)(WS - 1);
    float cx = (float)(t % WS) / (float)(WS - 1);
    if (threadIdx.x < 64) {
        float h = cy * w1[threadIdx.x*2+0] + cx * w1[threadIdx.x*2+1] + b1[threadIdx.x];
        hid[threadIdx.x] = fmaxf(h, 0.f);
    }
    __syncthreads();
    int c = threadIdx.x;
    float s = b2[c];
    #pragma unroll 8
    for (int j = 0; j < 64; j++) s += hid[j] * w2[c*64 + j];
    g_rel[t*CC + c] = s;
}

// ---------------- pos[w,t,c] = glob_pos windowed + rel[t,c] ---------------------
__global__ void pos_kernel(const float* __restrict__ gp)
{
    int idx = blockIdx.x * blockDim.x + threadIdx.x;
    if (idx >= NW*TT*CC) return;
    int c = idx % CC;
    int t = (idx / CC) % TT;
    int w = idx / (CC*TT);
    int wy = w / NWW, wx = w % NWW, ty = t / WS, tx = t % WS;
    g_pos[idx] = gp[(c*HH + wy*WS + ty)*WW + wx*WS + tx] + g_rel[t*CC + c];
}

// ---------------- valid[b,w] = maxpool(defe window) > 0 -------------------------
__global__ void valid_kernel(const float* __restrict__ defe)
{
    int bw = blockIdx.x;
    int b = bw / NW, w = bw % NW;
    int t = threadIdx.x;
    int wy = w / NWW, wx = w % NWW, ty = t / WS, tx = t % WS;
    float v = defe[(b*HH + wy*WS + ty)*WW + wx*WS + tx];
    __shared__ float red[256];
    red[t] = v; __syncthreads();
    for (int s = 128; s > 0; s >>= 1) {
        if (t < s) red[t] = fmaxf(red[t], red[t+s]);
        __syncthreads();
    }
    if (t == 0) g_valid[bw] = red[0] > 0.f ? 1.f : 0.f;
}

// ---------------- window partition: g_x[(b,w,t),c] = bm[b,c,y,x] ----------------
__global__ void partition_kernel(const float* __restrict__ bm)
{
    int idx = blockIdx.x * blockDim.x + threadIdx.x;
    if (idx >= NTOK*CC) return;
    int c = idx % CC;
    int tok = idx / CC;
    int t = tok % TT;
    int w = (tok / TT) % NW;
    int b = tok / (TT*NW);
    int wy = w / NWW, wx = w % NWW, ty = t / WS, tx = t % WS;
    g_x[idx] = bm[((size_t)(b*CC + c)*HH + wy*WS + ty)*WW + wx*WS + tx];
}

// ---------------- g_xp = g_x + pos ----------------------------------------------
__global__ void addpos_kernel()
{
    int idx = blockIdx.x * blockDim.x + threadIdx.x;
    if (idx >= NTOK*CC) return;
    int c = idx % CC;
    int tok = idx / CC;
    int t = tok % TT;
    int w = (tok / TT) % NW;
    g_xp[idx] = g_x[idx] + g_pos[(w*TT + t)*CC + c];
}

// ---------------- generic SGEMM: C[N,M] = A[N,K] @ Wt[M,K]^T + bias (opt relu) ---
// 64x64 tile, 256 threads, 4x4 per thread, 16-wide K tiles.
__global__ void gemm_kernel(const float* __restrict__ A, const float* __restrict__ Wt,
                            const float* __restrict__ bias, float* __restrict__ Cm,
                            int N, int M, int K, int relu)
{
    __shared__ float As[16][64];
    __shared__ float Bs[16][64];
    int tid = threadIdx.x;
    int tx = tid & 15, ty = tid >> 4;
    int n0 = blockIdx.y * 64, m0 = blockIdx.x * 64;
    int lr = tid >> 2;           // 0..63 row within tile
    int lc = (tid & 3) << 2;     // 0,4,8,12 k offset
    const float* Aload = A + (size_t)(n0 + lr) * K + lc;
    const float* Wload = Wt + (size_t)(m0 + lr) * K + lc;
    float acc[4][4] = {};
    for (int k0 = 0; k0 < K; k0 += 16) {
        float4 a4 = *(const float4*)(Aload + k0);
        float4 w4 = *(const float4*)(Wload + k0);
        As[lc+0][lr] = a4.x; As[lc+1][lr] = a4.y; As[lc+2][lr] = a4.z; As[lc+3][lr] = a4.w;
        Bs[lc+0][lr] = w4.x; Bs[lc+1][lr] = w4.y; Bs[lc+2][lr] = w4.z; Bs[lc+3][lr] = w4.w;
        __syncthreads();
        #pragma unroll
        for (int kk = 0; kk < 16; kk++) {
            float4 a = *(const float4*)&As[kk][ty << 2];
            float4 b = *(const float4*)&Bs[kk][tx << 2];
            acc[0][0] += a.x*b.x; acc[0][1] += a.x*b.y; acc[0][2] += a.x*b.z; acc[0][3] += a.x*b.w;
            acc[1][0] += a.y*b.x; acc[1][1] += a.y*b.y; acc[1][2] += a.y*b.z; acc[1][3] += a.y*b.w;
            acc[2][0] += a.z*b.x; acc[2][1] += a.z*b.y; acc[2][2] += a.z*b.z; acc[2][3] += a.z*b.w;
            acc[3][0] += a.w*b.x; acc[3][1] += a.w*b.y; acc[3][2] += a.w*b.z; acc[3][3] += a.w*b.w;
        }
        __syncthreads();
    }
    #pragma unroll
    for (int i = 0; i < 4; i++) {
        float4 o;
        float bs0 = bias[m0 + (tx<<2) + 0];
        float bs1 = bias[m0 + (tx<<2) + 1];
        float bs2 = bias[m0 + (tx<<2) + 2];
        float bs3 = bias[m0 + (tx<<2) + 3];
        o.x = acc[0+0][0]*0.f + acc[i][0] + bs0;  // keep simple: acc[i][j] + bias
        o.x = acc[i][0] + bs0; o.y = acc[i][1] + bs1;
        o.z = acc[i][2] + bs2; o.w = acc[i][3] + bs3;
        if (relu) {
            o.x = fmaxf(o.x, 0.f); o.y = fmaxf(o.y, 0.f);
            o.z = fmaxf(o.z, 0.f); o.w = fmaxf(o.w, 0.f);
        }
        *(float4*)&Cm[(size_t)(n0 + (ty<<2) + i) * M + m0 + (tx<<2)] = o;
    }
}

// ---------------- within-window attention (seq = T tokens, no mask) -------------
// grid (B*NW, NHEAD), 256 threads (one query each), online softmax, KV chunks of 128
__global__ void attn_within_kernel(const float* __restrict__ gq,
                                   const float* __restrict__ gk,
                                   const float* __restrict__ gv,
                                   float* __restrict__ gatt)
{
    __shared__ float ks[128*DH];
    __shared__ float vs[128*DH];
    int bw = blockIdx.x, h = blockIdx.y, t = threadIdx.x;
    size_t base = (size_t)bw * TT;
    const float scale = 0.17677669529663687f;   // 1/sqrt(32)
    float qr[DH];
    const float* qp = gq + (base + t)*CC + h*DH;
    #pragma unroll
    for (int d = 0; d < DH; d++) qr[d] = qp[d] * scale;
    float m = -INFINITY, s = 0.f, acc[DH] = {};
    for (int ch = 0; ch < 2; ch++) {
        __syncthreads();
        for (int i = threadIdx.x; i < 128*DH; i += 256) {
            int r = i / DH, d = i % DH;
            size_t tok = base + ch*128 + r;
            ks[i] = gk[tok*CC + h*DH + d];
            vs[i] = gv[tok*CC + h*DH + d];
        }
        __syncthreads();
        for (int i = 0; i < 128; i++) {
            float sc = 0.f;
            #pragma unroll
            for (int d = 0; d < DH; d++) sc += qr[d] * ks[i*DH + d];
            float mn = fmaxf(m, sc);
            float corr = __expf(m - mn);
            float e = __expf(sc - mn);
            s = s * corr + e;
            #pragma unroll
            for (int d = 0; d < DH; d++) acc[d] = acc[d]*corr + e*vs[i*DH + d];
            m = mn;
        }
    }
    float inv = s > 0.f ? 1.f / s : 0.f;
    float* op = gatt + (base + t)*CC + h*DH;
    #pragma unroll
    for (int d = 0; d < DH; d++) op[d] = acc[d] * inv;
}

// ---------------- cross-window attention (seq = NW windows, key padding mask) ---
// grid (B*T, NHEAD), 64 threads (one query window each)
__global__ void attn_cross_kernel(const float* __restrict__ gq,
                                  const float* __restrict__ gk,
                                  const float* __restrict__ gv,
                                  const float* __restrict__ gvalid,
                                  float* __restrict__ gatt)
{
    __shared__ float ks[NW*DH];
    __shared__ float vs[NW*DH];
    __shared__ float mk[NW];
    int bt = blockIdx.x;
    int b = bt / TT, t = bt % TT;
    int h = blockIdx.y;
    int wq = threadIdx.x;
    for (int i = threadIdx.x; i < NW*DH; i += 64) {
        int w = i / DH, d = i % DH;
        size_t tok = (size_t)(b*NW + w)*TT + t;
        ks[i] = gk[tok*CC + h*DH + d];
        vs[i] = gv[tok*CC + h*DH + d];
    }
    if (threadIdx.x < NW) mk[threadIdx.x] = gvalid[b*NW + threadIdx.x];
    __syncthreads();
    const float scale = 0.17677669529663687f;
    float qr[DH];
    size_t qtok = (size_t)(b*NW + wq)*TT + t;
    const float* qp = gq + qtok*CC + h*DH;
    #pragma unroll
    for (int d = 0; d < DH; d++) qr[d] = qp[d] * scale;
    float m = -INFINITY, s = 0.f, acc[DH] = {};
    for (int i = 0; i < NW; i++) {
        if (mk[i] == 0.f) continue;   // masked key
        float sc = 0.f;
        #pragma unroll
        for (int d = 0; d < DH; d++) sc += qr[d] * ks[i*DH + d];
        float mn = fmaxf(m, sc);
        float corr = __expf(m - mn);
        float e = __expf(sc - mn);
        s = s * corr + e;
        #pragma unroll
        for (int d = 0; d < DH; d++) acc[d] = acc[d]*corr + e*vs[i*DH + d];
        m = mn;
    }
    float inv = s > 0.f ? 1.f / s : 0.f;
    float* op = gatt + qtok*CC + h*DH;
    #pragma unroll
    for (int d = 0; d < DH; d++) op[d] = acc[d] * inv;
}

// ---------------- fused residual + LayerNorm: out = LN(a + r) * g + b ------------
__global__ void ln_kernel(const float* __restrict__ a, const float* __restrict__ r,
                          const float* __restrict__ g, const float* __restrict__ bb,
                          float* __restrict__ out)
{
    int tok = blockIdx.x;
    int c = threadIdx.x;
    size_t idx = (size_t)tok * CC + c;
    float v = a[idx] + r[idx];
    __shared__ float sh[256];
    sh[c] = v; __syncthreads();
    for (int s2 = 128; s2 > 0; s2 >>= 1) {
        if (c < s2) sh[c] += sh[c + s2];
        __syncthreads();
    }
    float mu = sh[0] * (1.f/CC);
    __syncthreads();
    float d = v - mu;
    sh[c] = d * d; __syncthreads();
    for (int s2 = 128; s2 > 0; s2 >>= 1) {
        if (c < s2) sh[c] += sh[c + s2];
        __syncthreads();
    }
    float var = sh[0] * (1.f/CC);
    out[idx] = d * rsqrtf(var + 1e-5f) * g[c] + bb[c];
}

// ---------------- final: out = backbone + window-scatter(x * valid) --------------
__global__ void output_kernel(const float* __restrict__ bm, float* __restrict__ out)
{
    int idx = blockIdx.x * blockDim.x + threadIdx.x;
    if (idx >= BB*CC*HH*WW) return;
    int xw = idx % WW;
    int y  = (idx / WW) % HH;
    int c  = (idx / (WW*HH)) % CC;
    int b  = idx / (WW*HH*CC);
    int wy = y / WS, ty = y % WS, wx = xw / WS, tx = xw % WS;
    int w = wy*NWW + wx;
    int t = ty*WS + tx;
    size_t tok = (size_t)(b*NW + w)*TT + t;
    out[idx] = bm[idx] + g_x[tok*CC + c] * g_valid[b*NW + w];
}

__global__ void valid_out_kernel(float* __restrict__ out)
{
    int i = threadIdx.x;   // 256 threads == B*NW
    out[(size_t)BB*CC*HH*WW + i] = g_valid[i];
}

// =================================================================================
extern "C" void kernel_launch(void* const* d_in, const int* in_sizes, int n_in,
                              void* d_out, int out_size)
{
    // Resolve REAL device addresses of scratch buffers (host-side names are
    // host shadows; on GB300 ATS would silently use host memory).
    float *p_x, *p_xp, *p_q, *p_k, *p_v, *p_att, *p_src, *p_ff, *p_valid;
    cudaGetSymbolAddress((void**)&p_x,    g_x);
    cudaGetSymbolAddress((void**)&p_xp,   g_xp);
    cudaGetSymbolAddress((void**)&p_q,    g_q);
    cudaGetSymbolAddress((void**)&p_k,    g_k);
    cudaGetSymbolAddress((void**)&p_v,    g_v);
    cudaGetSymbolAddress((void**)&p_att,  g_att);
    cudaGetSymbolAddress((void**)&p_src,  g_src);
    cudaGetSymbolAddress((void**)&p_ff,   g_ff);
    cudaGetSymbolAddress((void**)&p_valid, g_valid);

    // Input indexing: expected order has window_size (size-1) at index 2.
    // If the scalar was dropped from metadata, shift subsequent indices.
    int sh = (n_in > 2 && in_sizes[2] == 1) ? 0 : -1;
    const float* bm    = (const float*)d_in[0];   // backbone_memory [4,256,128,128]
    const float* defe  = (const float*)d_in[1];   // [4,1,128,128]
    const float* gp    = (const float*)d_in[3+sh];  // glob_pos_embed [256,128,128]
    const float* rw1   = (const float*)d_in[4+sh];
    const float* rb1   = (const float*)d_in[5+sh];
    const float* rw2   = (const float*)d_in[6+sh];
    const float* rb2   = (const float*)d_in[7+sh];
    const float* inw   = (const float*)d_in[8+sh];   // in_proj_w [768,256]
    const float* inb   = (const float*)d_in[9+sh];
    const float* ow    = (const float*)d_in[10+sh];  // out_proj_w [256,256]
    const float* ob    = (const float*)d_in[11+sh];
    const float* l1w   = (const float*)d_in[12+sh];  // [1024,256]
    const float* l1b   = (const float*)d_in[13+sh];
    const float* l2w   = (const float*)d_in[14+sh];  // [256,1024]
    const float* l2b   = (const float*)d_in[15+sh];
    const float* g1    = (const float*)d_in[16+sh];
    const float* b1    = (const float*)d_in[17+sh];
    const float* g2    = (const float*)d_in[18+sh];
    const float* b2    = (const float*)d_in[19+sh];

    const int EW = 256;                     // elementwise block size
    dim3 gEW_tokc((NTOK*CC + EW - 1)/EW);   // 65536 blocks

    // ---- prep ----
    rel_kernel<<<TT, 256>>>(rw1, rb1, rw2, rb2);
    pos_kernel<<<(NW*TT*CC + EW - 1)/EW, EW>>>(gp);
    valid_kernel<<<BB*NW, 256>>>(defe);
    partition_kernel<<<gEW_tokc, EW>>>(bm);

    for (int stage = 0; stage < 2; stage++) {
        // q,k inputs = x + pos ; v input = x
        addpos_kernel<<<gEW_tokc, EW>>>();
        // QKV projections
        gemm_kernel<<<dim3(CC/64, NTOK/64), 256>>>(p_xp, inw,            inb,       p_q, NTOK, CC, CC, 0);
        gemm_kernel<<<dim3(CC/64, NTOK/64), 256>>>(p_xp, inw + 256*256,  inb + 256, p_k, NTOK, CC, CC, 0);
        gemm_kernel<<<dim3(CC/64, NTOK/64), 256>>>(p_x,  inw + 512*256,  inb + 512, p_v, NTOK, CC, CC, 0);
        // attention
        if (stage == 0)
            attn_within_kernel<<<dim3(BB*NW, NHEAD), 256>>>(p_q, p_k, p_v, p_att);
        else
            attn_cross_kernel<<<dim3(BB*TT, NHEAD), 64>>>(p_q, p_k, p_v, p_valid, p_att);
        // output projection -> g_xp (temp y)
        gemm_kernel<<<dim3(CC/64, NTOK/64), 256>>>(p_att, ow, ob, p_xp, NTOK, CC, CC, 0);
        // src = LN(x + y)
        ln_kernel<<<NTOK, 256>>>(p_x, p_xp, g1, b1, p_src);
        // FFN
        gemm_kernel<<<dim3(DFF/64, NTOK/64), 256>>>(p_src, l1w, l1b, p_ff, NTOK, DFF, CC, 1);
        gemm_kernel<<<dim3(CC/64,  NTOK/64), 256>>>(p_ff,  l2w, l2b, p_xp, NTOK, CC, DFF, 0);
        // x = LN(src + ff)
        ln_kernel<<<NTOK, 256>>>(p_src, p_xp, g2, b2, p_x);
    }

    // ---- output ----
    output_kernel<<<(BB*CC*HH*WW + EW - 1)/EW, EW>>>(bm, (float*)d_out);
    if (out_size >= BB*CC*HH*WW + BB*NW)
        valid_out_kernel<<<1, BB*NW>>>((float*)d_out);
}

// round 3
// speedup vs baseline: 2.3485x; 2.3485x over previous
#include <cuda_runtime.h>
#include <math.h>
#include <stdint.h>

// Problem constants
#define BB 4
#define CC 256
#define HH 128
#define WW 128
#define WS 16
#define NWH 8
#define NWW 8
#define NW 64          // windows per image
#define TT 256         // tokens per window
#define NTOK (BB*NW*TT)  // 65536
#define NHEAD 8
#define DH 32
#define DFF 1024

// ---------------- device scratch (allocation-free: __device__ globals) ----------
// Host code must never pass these names directly as kernel args (host shadow +
// GB300 ATS would silently read host memory). Resolved via cudaGetSymbolAddress.
__device__ float g_x  [NTOK*CC];
__device__ float g_xp [NTOK*CC];
__device__ float g_q  [NTOK*CC];
__device__ float g_k  [NTOK*CC];
__device__ float g_v  [NTOK*CC];
__device__ float g_att[NTOK*CC];
__device__ float g_src[NTOK*CC];
__device__ float g_ff [NTOK*DFF];
__device__ float g_pos[NW*TT*CC];
__device__ float g_rel[TT*CC];
__device__ float g_valid[BB*NW];

// ---------------- rel position MLP:  [T,2] -> relu(64) -> [T,C] -----------------
__global__ void rel_kernel(const float* __restrict__ w1, const float* __restrict__ b1,
                           const float* __restrict__ w2, const float* __restrict__ b2)
{
    __shared__ float hid[64];
    int t = blockIdx.x;
    float cy = (float)(t / WS) / (float)(WS - 1);
    float cx = (float)(t % WS) / (float)(WS - 1);
    if (threadIdx.x < 64) {
        float h = cy * w1[threadIdx.x*2+0] + cx * w1[threadIdx.x*2+1] + b1[threadIdx.x];
        hid[threadIdx.x] = fmaxf(h, 0.f);
    }
    __syncthreads();
    int c = threadIdx.x;
    float s = b2[c];
    #pragma unroll 8
    for (int j = 0; j < 64; j++) s += hid[j] * w2[c*64 + j];
    g_rel[t*CC + c] = s;
}

// ---------------- pos[w,t,c] = glob_pos windowed + rel[t,c] ---------------------
__global__ void pos_kernel(const float* __restrict__ gp)
{
    int idx = blockIdx.x * blockDim.x + threadIdx.x;
    if (idx >= NW*TT*CC) return;
    int c = idx % CC;
    int t = (idx / CC) % TT;
    int w = idx / (CC*TT);
    int wy = w / NWW, wx = w % NWW, ty = t / WS, tx = t % WS;
    g_pos[idx] = gp[(c*HH + wy*WS + ty)*WW + wx*WS + tx] + g_rel[t*CC + c];
}

// ---------------- valid[b,w] = maxpool(defe window) > 0 -------------------------
__global__ void valid_kernel(const float* __restrict__ defe)
{
    int bw = blockIdx.x;
    int b = bw / NW, w = bw % NW;
    int t = threadIdx.x;
    int wy = w / NWW, wx = w % NWW, ty = t / WS, tx = t % WS;
    float v = defe[(b*HH + wy*WS + ty)*WW + wx*WS + tx];
    __shared__ float red[256];
    red[t] = v; __syncthreads();
    for (int s = 128; s > 0; s >>= 1) {
        if (t < s) red[t] = fmaxf(red[t], red[t+s]);
        __syncthreads();
    }
    if (t == 0) g_valid[bw] = red[0] > 0.f ? 1.f : 0.f;
}

// ---------------- window partition: g_x[(b,w,t),c] = bm[b,c,y,x] ----------------
__global__ void partition_kernel(const float* __restrict__ bm)
{
    int idx = blockIdx.x * blockDim.x + threadIdx.x;
    if (idx >= NTOK*CC) return;
    int c = idx % CC;
    int tok = idx / CC;
    int t = tok % TT;
    int w = (tok / TT) % NW;
    int b = tok / (TT*NW);
    int wy = w / NWW, wx = w % NWW, ty = t / WS, tx = t % WS;
    g_x[idx] = bm[((size_t)(b*CC + c)*HH + wy*WS + ty)*WW + wx*WS + tx];
}

// ---------------- g_xp = g_x + pos ----------------------------------------------
__global__ void addpos_kernel()
{
    int idx = blockIdx.x * blockDim.x + threadIdx.x;
    if (idx >= NTOK*CC) return;
    int c = idx % CC;
    int tok = idx / CC;
    int t = tok % TT;
    int w = (tok / TT) % NW;
    g_xp[idx] = g_x[idx] + g_pos[(w*TT + t)*CC + c];
}

// ================= TF32 tensor-core GEMM ========================================
// C[N,M] = A[N,K] @ Wt[M,K]^T + bias   (optional relu)
// Block tile 128(tok) x 128(out), BK=32, 8 warps: each warp 32x64 (2x8 m16n8k8).
// SMEM row stride 36 floats -> conflict-free fragment loads.

__device__ __forceinline__ uint32_t f2tf32(float x) {
    uint32_t u;
    asm("cvt.rna.tf32.f32 %0, %1;" : "=r"(u) : "f"(x));
    return u;
}

__device__ __forceinline__ void mma_tf32(float c[4], const uint32_t a[4], const uint32_t b[2]) {
    asm volatile(
        "mma.sync.aligned.m16n8k8.row.col.f32.tf32.tf32.f32 "
        "{%0,%1,%2,%3}, {%4,%5,%6,%7}, {%8,%9}, {%0,%1,%2,%3};"
        : "+f"(c[0]), "+f"(c[1]), "+f"(c[2]), "+f"(c[3])
        : "r"(a[0]), "r"(a[1]), "r"(a[2]), "r"(a[3]), "r"(b[0]), "r"(b[1]));
}

#define SSTRIDE 36

__global__ __launch_bounds__(256)
void gemm_tf32_kernel(const float* __restrict__ A, const float* __restrict__ Wt,
                      const float* __restrict__ bias, float* __restrict__ Cm,
                      int K, int M, int relu)
{
    __shared__ float As[128*SSTRIDE];
    __shared__ float Bs[128*SSTRIDE];
    int tid  = threadIdx.x;
    int n0   = blockIdx.y * 128;   // token block
    int m0   = blockIdx.x * 128;   // out-feature block
    int warp = tid >> 5, lane = tid & 31;
    int wm = (warp & 3) * 32;      // warp token offset
    int wn = (warp >> 2) * 64;     // warp out offset
    int g = lane >> 2, q = lane & 3;

    float c[2][8][4];
    #pragma unroll
    for (int i = 0; i < 2; i++)
        #pragma unroll
        for (int j = 0; j < 8; j++)
            #pragma unroll
            for (int r = 0; r < 4; r++) c[i][j][r] = 0.f;

    // staging: each thread loads 4x float4 per operand per tile
    int srow = tid >> 3;          // 0..31
    int skc  = (tid & 7) * 4;     // 0..28

    for (int k0 = 0; k0 < K; k0 += 32) {
        #pragma unroll
        for (int p = 0; p < 4; p++) {
            int row = p*32 + srow;
            float4 a4 = *(const float4*)(A  + (size_t)(n0 + row) * K + k0 + skc);
            float4 b4 = *(const float4*)(Wt + (size_t)(m0 + row) * K + k0 + skc);
            float* ad = &As[row*SSTRIDE + skc];
            float* bd = &Bs[row*SSTRIDE + skc];
            ad[0] = __uint_as_float(f2tf32(a4.x));
            ad[1] = __uint_as_float(f2tf32(a4.y));
            ad[2] = __uint_as_float(f2tf32(a4.z));
            ad[3] = __uint_as_float(f2tf32(a4.w));
            bd[0] = __uint_as_float(f2tf32(b4.x));
            bd[1] = __uint_as_float(f2tf32(b4.y));
            bd[2] = __uint_as_float(f2tf32(b4.z));
            bd[3] = __uint_as_float(f2tf32(b4.w));
        }
        __syncthreads();

        #pragma unroll
        for (int kk = 0; kk < 4; kk++) {
            int kb = kk * 8;
            uint32_t af[2][4];
            #pragma unroll
            for (int i = 0; i < 2; i++) {
                int r = wm + i*16 + g;
                af[i][0] = __float_as_uint(As[ r      *SSTRIDE + kb + q    ]);
                af[i][1] = __float_as_uint(As[(r + 8) *SSTRIDE + kb + q    ]);
                af[i][2] = __float_as_uint(As[ r      *SSTRIDE + kb + q + 4]);
                af[i][3] = __float_as_uint(As[(r + 8) *SSTRIDE + kb + q + 4]);
            }
            uint32_t bf[8][2];
            #pragma unroll
            for (int j = 0; j < 8; j++) {
                int n = wn + j*8 + g;
                bf[j][0] = __float_as_uint(Bs[n*SSTRIDE + kb + q    ]);
                bf[j][1] = __float_as_uint(Bs[n*SSTRIDE + kb + q + 4]);
            }
            #pragma unroll
            for (int i = 0; i < 2; i++)
                #pragma unroll
                for (int j = 0; j < 8; j++)
                    mma_tf32(c[i][j], af[i], bf[j]);
        }
        __syncthreads();
    }

    // epilogue: bias (+relu), store
    #pragma unroll
    for (int i = 0; i < 2; i++) {
        int row = n0 + wm + i*16 + g;
        #pragma unroll
        for (int j = 0; j < 8; j++) {
            int col = m0 + wn + j*8 + q*2;
            float b0 = bias[col], b1 = bias[col+1];
            float v0 = c[i][j][0] + b0, v1 = c[i][j][1] + b1;
            float v2 = c[i][j][2] + b0, v3 = c[i][j][3] + b1;
            if (relu) {
                v0 = fmaxf(v0, 0.f); v1 = fmaxf(v1, 0.f);
                v2 = fmaxf(v2, 0.f); v3 = fmaxf(v3, 0.f);
            }
            *(float2*)&Cm[(size_t) row      * M + col] = make_float2(v0, v1);
            *(float2*)&Cm[(size_t)(row + 8) * M + col] = make_float2(v2, v3);
        }
    }
}

// ---------------- within-window attention (seq = T tokens, no mask) -------------
__global__ void attn_within_kernel(const float* __restrict__ gq,
                                   const float* __restrict__ gk,
                                   const float* __restrict__ gv,
                                   float* __restrict__ gatt)
{
    __shared__ float ks[128*DH];
    __shared__ float vs[128*DH];
    int bw = blockIdx.x, h = blockIdx.y, t = threadIdx.x;
    size_t base = (size_t)bw * TT;
    const float scale = 0.17677669529663687f;   // 1/sqrt(32)
    float qr[DH];
    const float* qp = gq + (base + t)*CC + h*DH;
    #pragma unroll
    for (int d = 0; d < DH; d++) qr[d] = qp[d] * scale;
    float m = -INFINITY, s = 0.f, acc[DH] = {};
    for (int ch = 0; ch < 2; ch++) {
        __syncthreads();
        for (int i = threadIdx.x; i < 128*DH; i += 256) {
            int r = i / DH, d = i % DH;
            size_t tok = base + ch*128 + r;
            ks[i] = gk[tok*CC + h*DH + d];
            vs[i] = gv[tok*CC + h*DH + d];
        }
        __syncthreads();
        for (int i = 0; i < 128; i++) {
            float sc = 0.f;
            #pragma unroll
            for (int d = 0; d < DH; d++) sc += qr[d] * ks[i*DH + d];
            float mn = fmaxf(m, sc);
            float corr = __expf(m - mn);
            float e = __expf(sc - mn);
            s = s * corr + e;
            #pragma unroll
            for (int d = 0; d < DH; d++) acc[d] = acc[d]*corr + e*vs[i*DH + d];
            m = mn;
        }
    }
    float inv = s > 0.f ? 1.f / s : 0.f;
    float* op = gatt + (base + t)*CC + h*DH;
    #pragma unroll
    for (int d = 0; d < DH; d++) op[d] = acc[d] * inv;
}

// ---------------- cross-window attention (seq = NW windows, key padding mask) ---
__global__ void attn_cross_kernel(const float* __restrict__ gq,
                                  const float* __restrict__ gk,
                                  const float* __restrict__ gv,
                                  const float* __restrict__ gvalid,
                                  float* __restrict__ gatt)
{
    __shared__ float ks[NW*DH];
    __shared__ float vs[NW*DH];
    __shared__ float mk[NW];
    int bt = blockIdx.x;
    int b = bt / TT, t = bt % TT;
    int h = blockIdx.y;
    int wq = threadIdx.x;
    for (int i = threadIdx.x; i < NW*DH; i += 64) {
        int w = i / DH, d = i % DH;
        size_t tok = (size_t)(b*NW + w)*TT + t;
        ks[i] = gk[tok*CC + h*DH + d];
        vs[i] = gv[tok*CC + h*DH + d];
    }
    if (threadIdx.x < NW) mk[threadIdx.x] = gvalid[b*NW + threadIdx.x];
    __syncthreads();
    const float scale = 0.17677669529663687f;
    float qr[DH];
    size_t qtok = (size_t)(b*NW + wq)*TT + t;
    const float* qp = gq + qtok*CC + h*DH;
    #pragma unroll
    for (int d = 0; d < DH; d++) qr[d] = qp[d] * scale;
    float m = -INFINITY, s = 0.f, acc[DH] = {};
    for (int i = 0; i < NW; i++) {
        if (mk[i] == 0.f) continue;   // masked key
        float sc = 0.f;
        #pragma unroll
        for (int d = 0; d < DH; d++) sc += qr[d] * ks[i*DH + d];
        float mn = fmaxf(m, sc);
        float corr = __expf(m - mn);
        float e = __expf(sc - mn);
        s = s * corr + e;
        #pragma unroll
        for (int d = 0; d < DH; d++) acc[d] = acc[d]*corr + e*vs[i*DH + d];
        m = mn;
    }
    float inv = s > 0.f ? 1.f / s : 0.f;
    float* op = gatt + qtok*CC + h*DH;
    #pragma unroll
    for (int d = 0; d < DH; d++) op[d] = acc[d] * inv;
}

// ---------------- fused residual + LayerNorm: out = LN(a + r) * g + b ------------
__global__ void ln_kernel(const float* __restrict__ a, const float* __restrict__ r,
                          const float* __restrict__ g, const float* __restrict__ bb,
                          float* __restrict__ out)
{
    int tok = blockIdx.x;
    int c = threadIdx.x;
    size_t idx = (size_t)tok * CC + c;
    float v = a[idx] + r[idx];
    __shared__ float sh[256];
    sh[c] = v; __syncthreads();
    for (int s2 = 128; s2 > 0; s2 >>= 1) {
        if (c < s2) sh[c] += sh[c + s2];
        __syncthreads();
    }
    float mu = sh[0] * (1.f/CC);
    __syncthreads();
    float d = v - mu;
    sh[c] = d * d; __syncthreads();
    for (int s2 = 128; s2 > 0; s2 >>= 1) {
        if (c < s2) sh[c] += sh[c + s2];
        __syncthreads();
    }
    float var = sh[0] * (1.f/CC);
    out[idx] = d * rsqrtf(var + 1e-5f) * g[c] + bb[c];
}

// ---------------- final: out = backbone + window-scatter(x * valid) --------------
__global__ void output_kernel(const float* __restrict__ bm, float* __restrict__ out)
{
    int idx = blockIdx.x * blockDim.x + threadIdx.x;
    if (idx >= BB*CC*HH*WW) return;
    int xw = idx % WW;
    int y  = (idx / WW) % HH;
    int c  = (idx / (WW*HH)) % CC;
    int b  = idx / (WW*HH*CC);
    int wy = y / WS, ty = y % WS, wx = xw / WS, tx = xw % WS;
    int w = wy*NWW + wx;
    int t = ty*WS + tx;
    size_t tok = (size_t)(b*NW + w)*TT + t;
    out[idx] = bm[idx] + g_x[tok*CC + c] * g_valid[b*NW + w];
}

__global__ void valid_out_kernel(float* __restrict__ out)
{
    int i = threadIdx.x;   // 256 threads == B*NW
    out[(size_t)BB*CC*HH*WW + i] = g_valid[i];
}

// =================================================================================
extern "C" void kernel_launch(void* const* d_in, const int* in_sizes, int n_in,
                              void* d_out, int out_size)
{
    float *p_x, *p_xp, *p_q, *p_k, *p_v, *p_att, *p_src, *p_ff, *p_valid;
    cudaGetSymbolAddress((void**)&p_x,    g_x);
    cudaGetSymbolAddress((void**)&p_xp,   g_xp);
    cudaGetSymbolAddress((void**)&p_q,    g_q);
    cudaGetSymbolAddress((void**)&p_k,    g_k);
    cudaGetSymbolAddress((void**)&p_v,    g_v);
    cudaGetSymbolAddress((void**)&p_att,  g_att);
    cudaGetSymbolAddress((void**)&p_src,  g_src);
    cudaGetSymbolAddress((void**)&p_ff,   g_ff);
    cudaGetSymbolAddress((void**)&p_valid, g_valid);

    int sh = (n_in > 2 && in_sizes[2] == 1) ? 0 : -1;
    const float* bm    = (const float*)d_in[0];
    const float* defe  = (const float*)d_in[1];
    const float* gp    = (const float*)d_in[3+sh];
    const float* rw1   = (const float*)d_in[4+sh];
    const float* rb1   = (const float*)d_in[5+sh];
    const float* rw2   = (const float*)d_in[6+sh];
    const float* rb2   = (const float*)d_in[7+sh];
    const float* inw   = (const float*)d_in[8+sh];
    const float* inb   = (const float*)d_in[9+sh];
    const float* ow    = (const float*)d_in[10+sh];
    const float* ob    = (const float*)d_in[11+sh];
    const float* l1w   = (const float*)d_in[12+sh];
    const float* l1b   = (const float*)d_in[13+sh];
    const float* l2w   = (const float*)d_in[14+sh];
    const float* l2b   = (const float*)d_in[15+sh];
    const float* g1    = (const float*)d_in[16+sh];
    const float* b1    = (const float*)d_in[17+sh];
    const float* g2    = (const float*)d_in[18+sh];
    const float* b2    = (const float*)d_in[19+sh];

    const int EW = 256;
    dim3 gEW_tokc((NTOK*CC + EW - 1)/EW);

    // ---- prep ----
    rel_kernel<<<TT, 256>>>(rw1, rb1, rw2, rb2);
    pos_kernel<<<(NW*TT*CC + EW - 1)/EW, EW>>>(gp);
    valid_kernel<<<BB*NW, 256>>>(defe);
    partition_kernel<<<gEW_tokc, EW>>>(bm);

    dim3 gQKV(CC/128,  NTOK/128);   // (2, 512)
    dim3 gFF1(DFF/128, NTOK/128);   // (8, 512)

    for (int stage = 0; stage < 2; stage++) {
        addpos_kernel<<<gEW_tokc, EW>>>();
        // QKV projections (tensor cores, tf32)
        gemm_tf32_kernel<<<gQKV, 256>>>(p_xp, inw,            inb,       p_q, CC, CC, 0);
        gemm_tf32_kernel<<<gQKV, 256>>>(p_xp, inw + 256*256,  inb + 256, p_k, CC, CC, 0);
        gemm_tf32_kernel<<<gQKV, 256>>>(p_x,  inw + 512*256,  inb + 512, p_v, CC, CC, 0);
        // attention
        if (stage == 0)
            attn_within_kernel<<<dim3(BB*NW, NHEAD), 256>>>(p_q, p_k, p_v, p_att);
        else
            attn_cross_kernel<<<dim3(BB*TT, NHEAD), 64>>>(p_q, p_k, p_v, p_valid, p_att);
        // output projection
        gemm_tf32_kernel<<<gQKV, 256>>>(p_att, ow, ob, p_xp, CC, CC, 0);
        // src = LN(x + y)
        ln_kernel<<<NTOK, 256>>>(p_x, p_xp, g1, b1, p_src);
        // FFN
        gemm_tf32_kernel<<<gFF1, 256>>>(p_src, l1w, l1b, p_ff, CC,  DFF, 1);
        gemm_tf32_kernel<<<gQKV, 256>>>(p_ff,  l2w, l2b, p_xp, DFF, CC,  0);
        // x = LN(src + ff)
        ln_kernel<<<NTOK, 256>>>(p_src, p_xp, g2, b2, p_x);
    }

    // ---- output ----
    output_kernel<<<(BB*CC*HH*WW + EW - 1)/EW, EW>>>(bm, (float*)d_out);
    if (out_size >= BB*CC*HH*WW + BB*NW)
        valid_out_kernel<<<1, BB*NW>>>((float*)d_out);
}

// round 4
// speedup vs baseline: 3.3192x; 1.4133x over previous
#include <cuda_runtime.h>
#include <math.h>
#include <stdint.h>

// Problem constants
#define BB 4
#define CC 256
#define HH 128
#define WW 128
#define WS 16
#define NWH 8
#define NWW 8
#define NW 64
#define TT 256
#define NTOK (BB*NW*TT)  // 65536
#define NHEAD 8
#define DH 32
#define DFF 1024

// ---------------- device scratch (allocation-free: __device__ globals) ----------
// Never pass these names directly as kernel args from host (host shadow + GB300
// ATS silently reads host memory). Resolved via cudaGetSymbolAddress.
__device__ float g_x  [NTOK*CC];
__device__ float g_xp [NTOK*CC];
__device__ float g_qkv[NTOK*768];
__device__ float g_att[NTOK*CC];
__device__ float g_src[NTOK*CC];
__device__ float g_ff [NTOK*DFF];
__device__ float g_pos[NW*TT*CC];
__device__ float g_rel[TT*CC];
__device__ float g_valid[BB*NW];

// ---------------- rel position MLP ----------------------------------------------
__global__ void rel_kernel(const float* __restrict__ w1, const float* __restrict__ b1,
                           const float* __restrict__ w2, const float* __restrict__ b2)
{
    __shared__ float hid[64];
    int t = blockIdx.x;
    float cy = (float)(t / WS) / (float)(WS - 1);
    float cx = (float)(t % WS) / (float)(WS - 1);
    if (threadIdx.x < 64) {
        float h = cy * w1[threadIdx.x*2+0] + cx * w1[threadIdx.x*2+1] + b1[threadIdx.x];
        hid[threadIdx.x] = fmaxf(h, 0.f);
    }
    __syncthreads();
    int c = threadIdx.x;
    float s = b2[c];
    #pragma unroll 8
    for (int j = 0; j < 64; j++) s += hid[j] * w2[c*64 + j];
    g_rel[t*CC + c] = s;
}

// ---------------- pos[w,t,c] = glob_pos windowed + rel[t,c] ---------------------
__global__ void pos_kernel(const float* __restrict__ gp)
{
    int idx = blockIdx.x * blockDim.x + threadIdx.x;
    if (idx >= NW*TT*CC) return;
    int c = idx % CC;
    int t = (idx / CC) % TT;
    int w = idx / (CC*TT);
    int wy = w / NWW, wx = w % NWW, ty = t / WS, tx = t % WS;
    g_pos[idx] = gp[(c*HH + wy*WS + ty)*WW + wx*WS + tx] + g_rel[t*CC + c];
}

// ---------------- valid[b,w] = maxpool(defe window) > 0 -------------------------
__global__ void valid_kernel(const float* __restrict__ defe)
{
    int bw = blockIdx.x;
    int b = bw / NW, w = bw % NW;
    int t = threadIdx.x;
    int wy = w / NWW, wx = w % NWW, ty = t / WS, tx = t % WS;
    float v = defe[(b*HH + wy*WS + ty)*WW + wx*WS + tx];
    __shared__ float red[256];
    red[t] = v; __syncthreads();
    for (int s = 128; s > 0; s >>= 1) {
        if (t < s) red[t] = fmaxf(red[t], red[t+s]);
        __syncthreads();
    }
    if (t == 0) g_valid[bw] = red[0] > 0.f ? 1.f : 0.f;
}

// ---------------- window partition (tiled transpose) -----------------------------
// grid (4 xt, 128 y, 32 = b*8+ct), block 256
__global__ void partition_kernel(const float* __restrict__ bm)
{
    __shared__ float tile[32][33];
    int xt = blockIdx.x, y = blockIdx.y;
    int b = blockIdx.z >> 3, ct = blockIdx.z & 7;
    int c0 = ct * 32, x0 = xt * 32;
    int ci = threadIdx.x >> 5, xi = threadIdx.x & 31;
    #pragma unroll
    for (int p = 0; p < 4; p++) {
        int c = ci + p*8;
        tile[c][xi] = bm[((size_t)(b*CC + c0 + c)*HH + y)*WW + x0 + xi];
    }
    __syncthreads();
    int wy = y >> 4, ty = y & 15;
    #pragma unroll
    for (int p = 0; p < 4; p++) {
        int xj = ci + p*8;
        int x = x0 + xj;
        int w = wy*8 + (x >> 4);
        int t = ty*16 + (x & 15);
        g_x[((size_t)(b*NW + w)*TT + t)*CC + c0 + xi] = tile[xi][xj];
    }
}

// ---------------- g_xp = g_x + pos (float4) --------------------------------------
__global__ void addpos_kernel()
{
    int i4 = blockIdx.x * blockDim.x + threadIdx.x;   // float4 index
    if (i4 >= NTOK*CC/4) return;
    int c4  = i4 & 63;            // 64 float4 per token
    int tok = i4 >> 6;
    int wt  = tok & (NW*TT - 1);
    float4 x = ((const float4*)g_x)[i4];
    float4 p = ((const float4*)g_pos)[wt*64 + c4];
    x.x += p.x; x.y += p.y; x.z += p.z; x.w += p.w;
    ((float4*)g_xp)[i4] = x;
}

// ================= TF32 tensor-core GEMM (cp.async double-buffered) ==============
// C[n, m0+*] (ldC) = A[n,K] @ Wt[m,K]^T + bias, optional relu.
// Block 128x128, BK=32, 8 warps each 32x64 (2x8 m16n8k8).
// Raw fp32 bits fed to HMMA.TF32 (HW truncates to tf32).

__device__ __forceinline__ void mma_tf32(float c[4], const uint32_t a[4], const uint32_t b[2]) {
    asm volatile(
        "mma.sync.aligned.m16n8k8.row.col.f32.tf32.tf32.f32 "
        "{%0,%1,%2,%3}, {%4,%5,%6,%7}, {%8,%9}, {%0,%1,%2,%3};"
        : "+f"(c[0]), "+f"(c[1]), "+f"(c[2]), "+f"(c[3])
        : "r"(a[0]), "r"(a[1]), "r"(a[2]), "r"(a[3]), "r"(b[0]), "r"(b[1]));
}

__device__ __forceinline__ void cp_async16(uint32_t dst, const void* src) {
    asm volatile("cp.async.cg.shared.global [%0], [%1], 16;" :: "r"(dst), "l"(src));
}

__global__ __launch_bounds__(256)
void gemm_tf32(const float* __restrict__ A0, const float* __restrict__ A1, int mswitch,
               const float* __restrict__ Wt, const float* __restrict__ bias,
               float* __restrict__ C, int ldC, int K, int relu)
{
    extern __shared__ float sm[];
    float* As = sm;            // [2][4096]
    float* Bs = sm + 8192;     // [2][4096]
    int tid = threadIdx.x;
    int n0 = blockIdx.y * 128;
    int m0 = blockIdx.x * 128;
    const float* A = (m0 < mswitch) ? A0 : A1;
    int warp = tid >> 5, lane = tid & 31;
    int wm = (warp & 3) << 5;
    int wn = (warp >> 2) << 6;
    int g = lane >> 2, q = lane & 3;

    int srow = tid >> 3;       // 0..31
    int scb  = tid & 7;        // col-block (4 floats)

    uint32_t asB = (uint32_t)__cvta_generic_to_shared(As);
    uint32_t bsB = (uint32_t)__cvta_generic_to_shared(Bs);

    float c[2][8][4] = {};
    int nk = K >> 5;

#define LOAD_STAGE(st, k0)                                                          \
    {                                                                               \
        _Pragma("unroll")                                                           \
        for (int p = 0; p < 4; p++) {                                               \
            int row = (p << 5) + srow;                                              \
            int sof = ((st)*4096 + (row << 5) + (((scb ^ (row & 7)) << 2))) << 2;   \
            cp_async16(asB + sof, A  + (size_t)(n0 + row) * K + (k0) + (scb << 2)); \
            cp_async16(bsB + sof, Wt + (size_t)(m0 + row) * K + (k0) + (scb << 2)); \
        }                                                                           \
        asm volatile("cp.async.commit_group;");                                     \
    }

    LOAD_STAGE(0, 0)
    for (int kt = 0; kt < nk; kt++) {
        int cur = kt & 1;
        if (kt + 1 < nk) {
            LOAD_STAGE(cur ^ 1, (kt + 1) << 5)
            asm volatile("cp.async.wait_group 1;");
        } else {
            asm volatile("cp.async.wait_group 0;");
        }
        __syncthreads();
        const float* Ac = As + cur*4096;
        const float* Bc = Bs + cur*4096;
        #pragma unroll
        for (int kk = 0; kk < 4; kk++) {
            int cb0 = kk << 1, cb1 = cb0 + 1;
            uint32_t af[2][4];
            #pragma unroll
            for (int i = 0; i < 2; i++) {
                int r0 = wm + (i << 4) + g, r1 = r0 + 8;
                af[i][0] = __float_as_uint(Ac[(r0 << 5) + ((cb0 ^ (r0 & 7)) << 2) + q]);
                af[i][1] = __float_as_uint(Ac[(r1 << 5) + ((cb0 ^ (r1 & 7)) << 2) + q]);
                af[i][2] = __float_as_uint(Ac[(r0 << 5) + ((cb1 ^ (r0 & 7)) << 2) + q]);
                af[i][3] = __float_as_uint(Ac[(r1 << 5) + ((cb1 ^ (r1 & 7)) << 2) + q]);
            }
            uint32_t bf[8][2];
            #pragma unroll
            for (int j = 0; j < 8; j++) {
                int n = wn + (j << 3) + g;
                bf[j][0] = __float_as_uint(Bc[(n << 5) + ((cb0 ^ (n & 7)) << 2) + q]);
                bf[j][1] = __float_as_uint(Bc[(n << 5) + ((cb1 ^ (n & 7)) << 2) + q]);
            }
            #pragma unroll
            for (int i = 0; i < 2; i++)
                #pragma unroll
                for (int j = 0; j < 8; j++)
                    mma_tf32(c[i][j], af[i], bf[j]);
        }
        __syncthreads();
    }
#undef LOAD_STAGE

    #pragma unroll
    for (int i = 0; i < 2; i++) {
        int row = n0 + wm + (i << 4) + g;
        #pragma unroll
        for (int j = 0; j < 8; j++) {
            int col = m0 + wn + (j << 3) + (q << 1);
            float b0 = bias[col], b1 = bias[col+1];
            float v0 = c[i][j][0] + b0, v1 = c[i][j][1] + b1;
            float v2 = c[i][j][2] + b0, v3 = c[i][j][3] + b1;
            if (relu) {
                v0 = fmaxf(v0, 0.f); v1 = fmaxf(v1, 0.f);
                v2 = fmaxf(v2, 0.f); v3 = fmaxf(v3, 0.f);
            }
            *(float2*)&C[(size_t) row      * ldC + col] = make_float2(v0, v1);
            *(float2*)&C[(size_t)(row + 8) * ldC + col] = make_float2(v2, v3);
        }
    }
}

// ---------------- within-window attention (qkv combined, stride 768) -------------
__global__ void attn_within_kernel(const float* __restrict__ qkv, float* __restrict__ gatt)
{
    __shared__ float ks[128*DH];
    __shared__ float vs[128*DH];
    int bw = blockIdx.x, h = blockIdx.y, t = threadIdx.x;
    size_t base = (size_t)bw * TT;
    const float scale = 0.17677669529663687f;
    float qr[DH];
    const float* qp = qkv + (base + t)*768 + h*DH;
    #pragma unroll
    for (int d = 0; d < DH; d++) qr[d] = qp[d] * scale;
    float m = -INFINITY, s = 0.f, acc[DH] = {};
    for (int ch = 0; ch < 2; ch++) {
        __syncthreads();
        for (int i = threadIdx.x; i < 128*8; i += 256) {
            int r = i >> 3, d = i & 7;
            size_t rb = (base + ch*128 + r)*768 + h*DH;
            ((float4*)ks)[i] = *((const float4*)(qkv + rb + 256) + d);
            ((float4*)vs)[i] = *((const float4*)(qkv + rb + 512) + d);
        }
        __syncthreads();
        for (int i = 0; i < 128; i++) {
            float sc = 0.f;
            #pragma unroll
            for (int d = 0; d < DH; d++) sc += qr[d] * ks[i*DH + d];
            float mn = fmaxf(m, sc);
            float corr = __expf(m - mn);
            float e = __expf(sc - mn);
            s = s * corr + e;
            #pragma unroll
            for (int d = 0; d < DH; d++) acc[d] = acc[d]*corr + e*vs[i*DH + d];
            m = mn;
        }
    }
    float inv = s > 0.f ? 1.f / s : 0.f;
    float* op = gatt + (base + t)*CC + h*DH;
    #pragma unroll
    for (int d = 0; d < DH; d++) op[d] = acc[d] * inv;
}

// ---------------- cross-window attention (key padding mask) ----------------------
__global__ void attn_cross_kernel(const float* __restrict__ qkv,
                                  const float* __restrict__ gvalid,
                                  float* __restrict__ gatt)
{
    __shared__ float ks[NW*DH];
    __shared__ float vs[NW*DH];
    __shared__ float mk[NW];
    int bt = blockIdx.x;
    int b = bt / TT, t = bt % TT;
    int h = blockIdx.y;
    int wq = threadIdx.x;
    for (int i = threadIdx.x; i < NW*8; i += 64) {
        int w = i >> 3, d = i & 7;
        size_t rb = ((size_t)(b*NW + w)*TT + t)*768 + h*DH;
        ((float4*)ks)[i] = *((const float4*)(qkv + rb + 256) + d);
        ((float4*)vs)[i] = *((const float4*)(qkv + rb + 512) + d);
    }
    if (threadIdx.x < NW) mk[threadIdx.x] = gvalid[b*NW + threadIdx.x];
    __syncthreads();
    const float scale = 0.17677669529663687f;
    float qr[DH];
    size_t qtok = (size_t)(b*NW + wq)*TT + t;
    const float* qp = qkv + qtok*768 + h*DH;
    #pragma unroll
    for (int d = 0; d < DH; d++) qr[d] = qp[d] * scale;
    float m = -INFINITY, s = 0.f, acc[DH] = {};
    for (int i = 0; i < NW; i++) {
        if (mk[i] == 0.f) continue;
        float sc = 0.f;
        #pragma unroll
        for (int d = 0; d < DH; d++) sc += qr[d] * ks[i*DH + d];
        float mn = fmaxf(m, sc);
        float corr = __expf(m - mn);
        float e = __expf(sc - mn);
        s = s * corr + e;
        #pragma unroll
        for (int d = 0; d < DH; d++) acc[d] = acc[d]*corr + e*vs[i*DH + d];
        m = mn;
    }
    float inv = s > 0.f ? 1.f / s : 0.f;
    float* op = gatt + qtok*CC + h*DH;
    #pragma unroll
    for (int d = 0; d < DH; d++) op[d] = acc[d] * inv;
}

// ---------------- fused residual + LayerNorm (warp per token) --------------------
// grid NTOK/8, block 256
__global__ void ln_kernel(const float* __restrict__ a, const float* __restrict__ r,
                          const float* __restrict__ g, const float* __restrict__ bb,
                          float* __restrict__ out)
{
    int warp = threadIdx.x >> 5, lane = threadIdx.x & 31;
    size_t tok = (size_t)blockIdx.x * 8 + warp;
    size_t base = tok * CC;
    float4 x0 = *(const float4*)(a + base + lane*4);
    float4 x1 = *(const float4*)(a + base + 128 + lane*4);
    float4 r0 = *(const float4*)(r + base + lane*4);
    float4 r1 = *(const float4*)(r + base + 128 + lane*4);
    x0.x += r0.x; x0.y += r0.y; x0.z += r0.z; x0.w += r0.w;
    x1.x += r1.x; x1.y += r1.y; x1.z += r1.z; x1.w += r1.w;
    float sum = x0.x+x0.y+x0.z+x0.w + x1.x+x1.y+x1.z+x1.w;
    float sq  = x0.x*x0.x+x0.y*x0.y+x0.z*x0.z+x0.w*x0.w
              + x1.x*x1.x+x1.y*x1.y+x1.z*x1.z+x1.w*x1.w;
    #pragma unroll
    for (int o = 16; o > 0; o >>= 1) {
        sum += __shfl_xor_sync(0xffffffffu, sum, o);
        sq  += __shfl_xor_sync(0xffffffffu, sq,  o);
    }
    float mu  = sum * (1.f/CC);
    float var = sq  * (1.f/CC) - mu*mu;
    float inv = rsqrtf(var + 1e-5f);
    float4 g0 = *(const float4*)(g  + lane*4);
    float4 g1 = *(const float4*)(g  + 128 + lane*4);
    float4 b0 = *(const float4*)(bb + lane*4);
    float4 b1 = *(const float4*)(bb + 128 + lane*4);
    float4 o0, o1;
    o0.x = (x0.x-mu)*inv*g0.x + b0.x; o0.y = (x0.y-mu)*inv*g0.y + b0.y;
    o0.z = (x0.z-mu)*inv*g0.z + b0.z; o0.w = (x0.w-mu)*inv*g0.w + b0.w;
    o1.x = (x1.x-mu)*inv*g1.x + b1.x; o1.y = (x1.y-mu)*inv*g1.y + b1.y;
    o1.z = (x1.z-mu)*inv*g1.z + b1.z; o1.w = (x1.w-mu)*inv*g1.w + b1.w;
    *(float4*)(out + base + lane*4)       = o0;
    *(float4*)(out + base + 128 + lane*4) = o1;
}

// ---------------- final scatter (tiled transpose): out = bm + x*valid ------------
// grid (4 xt, 128 y, 32 = b*8+ct), block 256
__global__ void output_kernel(const float* __restrict__ bm, float* __restrict__ out)
{
    __shared__ float tile[32][33];
    int xt = blockIdx.x, y = blockIdx.y;
    int b = blockIdx.z >> 3, ct = blockIdx.z & 7;
    int c0 = ct * 32, x0 = xt * 32;
    int wy = y >> 4, ty = y & 15;
    int hi = threadIdx.x >> 5, lane = threadIdx.x & 31;
    #pragma unroll
    for (int p = 0; p < 4; p++) {
        int xj = hi + p*8;
        int x = x0 + xj;
        int w = wy*8 + (x >> 4);
        int t = ty*16 + (x & 15);
        tile[xj][lane] = g_x[((size_t)(b*NW + w)*TT + t)*CC + c0 + lane] * g_valid[b*NW + w];
    }
    __syncthreads();
    #pragma unroll
    for (int p = 0; p < 4; p++) {
        int c = hi + p*8;
        size_t idx = ((size_t)(b*CC + c0 + c)*HH + y)*WW + x0 + lane;
        out[idx] = bm[idx] + tile[lane][c];
    }
}

__global__ void valid_out_kernel(float* __restrict__ out)
{
    int i = threadIdx.x;
    out[(size_t)BB*CC*HH*WW + i] = g_valid[i];
}

// =================================================================================
extern "C" void kernel_launch(void* const* d_in, const int* in_sizes, int n_in,
                              void* d_out, int out_size)
{
    float *p_x, *p_xp, *p_qkv, *p_att, *p_src, *p_ff, *p_valid;
    cudaGetSymbolAddress((void**)&p_x,    g_x);
    cudaGetSymbolAddress((void**)&p_xp,   g_xp);
    cudaGetSymbolAddress((void**)&p_qkv,  g_qkv);
    cudaGetSymbolAddress((void**)&p_att,  g_att);
    cudaGetSymbolAddress((void**)&p_src,  g_src);
    cudaGetSymbolAddress((void**)&p_ff,   g_ff);
    cudaGetSymbolAddress((void**)&p_valid, g_valid);

    static int smem_set = 0;
    if (!smem_set) {
        cudaFuncSetAttribute(gemm_tf32, cudaFuncAttributeMaxDynamicSharedMemorySize, 65536);
        smem_set = 1;
    }

    int sh = (n_in > 2 && in_sizes[2] == 1) ? 0 : -1;
    const float* bm    = (const float*)d_in[0];
    const float* defe  = (const float*)d_in[1];
    const float* gp    = (const float*)d_in[3+sh];
    const float* rw1   = (const float*)d_in[4+sh];
    const float* rb1   = (const float*)d_in[5+sh];
    const float* rw2   = (const float*)d_in[6+sh];
    const float* rb2   = (const float*)d_in[7+sh];
    const float* inw   = (const float*)d_in[8+sh];
    const float* inb   = (const float*)d_in[9+sh];
    const float* ow    = (const float*)d_in[10+sh];
    const float* ob    = (const float*)d_in[11+sh];
    const float* l1w   = (const float*)d_in[12+sh];
    const float* l1b   = (const float*)d_in[13+sh];
    const float* l2w   = (const float*)d_in[14+sh];
    const float* l2b   = (const float*)d_in[15+sh];
    const float* g1    = (const float*)d_in[16+sh];
    const float* b1    = (const float*)d_in[17+sh];
    const float* g2    = (const float*)d_in[18+sh];
    const float* b2    = (const float*)d_in[19+sh];

    // ---- prep ----
    rel_kernel<<<TT, 256>>>(rw1, rb1, rw2, rb2);
    pos_kernel<<<(NW*TT*CC + 255)/256, 256>>>(gp);
    valid_kernel<<<BB*NW, 256>>>(defe);
    partition_kernel<<<dim3(4, 128, 32), 256>>>(bm);

    dim3 gQKV(6, NTOK/128);
    dim3 gOP (2, NTOK/128);
    dim3 gFF1(8, NTOK/128);
    const int GSM = 65536;

    for (int stage = 0; stage < 2; stage++) {
        addpos_kernel<<<(NTOK*CC/4 + 255)/256, 256>>>();
        // fused QKV: Q,K blocks (m0<512) read x+pos; V blocks read x
        gemm_tf32<<<gQKV, 256, GSM>>>(p_xp, p_x, 512, inw, inb, p_qkv, 768, CC, 0);
        if (stage == 0)
            attn_within_kernel<<<dim3(BB*NW, NHEAD), 256>>>(p_qkv, p_att);
        else
            attn_cross_kernel<<<dim3(BB*TT, NHEAD), 64>>>(p_qkv, p_valid, p_att);
        gemm_tf32<<<gOP, 256, GSM>>>(p_att, p_att, 0, ow, ob, p_xp, CC, CC, 0);
        ln_kernel<<<NTOK/8, 256>>>(p_x, p_xp, g1, b1, p_src);
        gemm_tf32<<<gFF1, 256, GSM>>>(p_src, p_src, 0, l1w, l1b, p_ff, DFF, CC, 1);
        gemm_tf32<<<gOP, 256, GSM>>>(p_ff, p_ff, 0, l2w, l2b, p_xp, CC, DFF, 0);
        ln_kernel<<<NTOK/8, 256>>>(p_src, p_xp, g2, b2, p_x);
    }

    // ---- output ----
    output_kernel<<<dim3(4, 128, 32), 256>>>(bm, (float*)d_out);
    if (out_size >= BB*CC*HH*WW + BB*NW)
        valid_out_kernel<<<1, BB*NW>>>((float*)d_out);
}